// round 7
// baseline (speedup 1.0000x reference)
#include <cuda_runtime.h>
#include <cuda_bf16.h>
#include <math.h>

// Problem constants
#define Bb   2
#define Tt   2048
#define Cc   2048
#define NH   16
#define NKV  4
#define HD   128
#define Mrows (Bb * Tt)        // 4096

typedef unsigned short u16;
typedef unsigned int   u32;
typedef unsigned long long u64;

// ---------------------------------------------------------------------------
// Scratch (device globals; allocation-free)
// ---------------------------------------------------------------------------
__device__ u16 g_xh[(size_t)Mrows * Cc];
__device__ u16 g_xl[(size_t)Mrows * Cc];
__device__ u16 g_WqTh[(size_t)Cc * Cc],  g_WqTl[(size_t)Cc * Cc];
__device__ u16 g_WkTh[(size_t)512 * Cc], g_WkTl[(size_t)512 * Cc];
__device__ u16 g_WvTh[(size_t)512 * Cc], g_WvTl[(size_t)512 * Cc];
__device__ u16 g_WoTh[(size_t)Cc * Cc],  g_WoTl[(size_t)Cc * Cc];
__device__ u16 g_Qh[(size_t)Mrows * Cc], g_Ql[(size_t)Mrows * Cc];
__device__ u16 g_Kh[(size_t)Mrows * 512], g_Kl[(size_t)Mrows * 512];
__device__ u16 g_Vh[(size_t)Mrows * 512], g_Vl[(size_t)Mrows * 512];
__device__ u16 g_Yh[(size_t)Mrows * Cc], g_Yl[(size_t)Mrows * Cc];

// ---------------------------------------------------------------------------
// Helpers
// ---------------------------------------------------------------------------
__device__ __forceinline__ void bsplit(float f, u16& h, u16& l) {
    __nv_bfloat16 bh = __float2bfloat16_rn(f);
    float fh = __bfloat162float(bh);
    __nv_bfloat16 bl = __float2bfloat16_rn(f - fh);
    h = __bfloat16_as_ushort(bh);
    l = __bfloat16_as_ushort(bl);
}

__device__ __forceinline__ void ldsm4(unsigned* r, unsigned addr) {
    asm volatile("ldmatrix.sync.aligned.m8n8.x4.shared.b16 {%0,%1,%2,%3}, [%4];\n"
                 : "=r"(r[0]), "=r"(r[1]), "=r"(r[2]), "=r"(r[3]) : "r"(addr));
}
__device__ __forceinline__ void ldsm4t(unsigned* r, unsigned addr) {
    asm volatile("ldmatrix.sync.aligned.m8n8.x4.trans.shared.b16 {%0,%1,%2,%3}, [%4];\n"
                 : "=r"(r[0]), "=r"(r[1]), "=r"(r[2]), "=r"(r[3]) : "r"(addr));
}
__device__ __forceinline__ void mma_bf16(float* c, const unsigned* a,
                                         unsigned b0, unsigned b1) {
    asm volatile(
        "mma.sync.aligned.m16n8k16.row.col.f32.bf16.bf16.f32 "
        "{%0,%1,%2,%3}, {%4,%5,%6,%7}, {%8,%9}, {%0,%1,%2,%3};\n"
        : "+f"(c[0]), "+f"(c[1]), "+f"(c[2]), "+f"(c[3])
        : "r"(a[0]), "r"(a[1]), "r"(a[2]), "r"(a[3]), "r"(b0), "r"(b1));
}

__device__ __forceinline__ void cpasync16(u32 dst, const void* src) {
    asm volatile("cp.async.cg.shared.global [%0], [%1], 16;"
                 :: "r"(dst), "l"(src) : "memory");
}
#define CP_COMMIT() asm volatile("cp.async.commit_group;" ::: "memory")
#define CP_WAIT1()  asm volatile("cp.async.wait_group 1;" ::: "memory")
#define CP_WAIT0()  asm volatile("cp.async.wait_group 0;" ::: "memory")

// ---------------------------------------------------------------------------
// Prep kernels
// ---------------------------------------------------------------------------
__global__ __launch_bounds__(256) void split_x_k(const float* __restrict__ x,
                                                 u16* __restrict__ xh,
                                                 u16* __restrict__ xl)
{
    size_t i = ((size_t)blockIdx.x * 256 + threadIdx.x) * 8;
    float4 a = *(const float4*)(x + i);
    float4 b = *(const float4*)(x + i + 4);
    float f[8] = {a.x, a.y, a.z, a.w, b.x, b.y, b.z, b.w};
    u16 hh[8], ll[8];
#pragma unroll
    for (int j = 0; j < 8; j++) bsplit(f[j], hh[j], ll[j]);
    uint4 H, L;
    H.x = hh[0] | (hh[1] << 16); H.y = hh[2] | (hh[3] << 16);
    H.z = hh[4] | (hh[5] << 16); H.w = hh[6] | (hh[7] << 16);
    L.x = ll[0] | (ll[1] << 16); L.y = ll[2] | (ll[3] << 16);
    L.z = ll[4] | (ll[5] << 16); L.w = ll[6] | (ll[7] << 16);
    *(uint4*)(xh + i) = H;
    *(uint4*)(xl + i) = L;
}

// W [K=2048, N] f32 -> WT [N, 2048] bf16 hi/lo
__global__ __launch_bounds__(256) void tsplit_k(const float* __restrict__ W,
                                                u16* __restrict__ Wth,
                                                u16* __restrict__ Wtl, int N)
{
    __shared__ float t[32][33];
    const int tx = threadIdx.x, ty = threadIdx.y;
    const int n = blockIdx.x * 32 + tx;
    const int k0 = blockIdx.y * 32;
#pragma unroll
    for (int i = 0; i < 4; i++)
        t[ty + 8 * i][tx] = W[(size_t)(k0 + ty + 8 * i) * N + n];
    __syncthreads();
    const int nw = blockIdx.x * 32;
    const int kk = k0 + tx;
#pragma unroll
    for (int i = 0; i < 4; i++) {
        float v = t[tx][ty + 8 * i];
        u16 h, l;
        bsplit(v, h, l);
        Wth[(size_t)(nw + ty + 8 * i) * 2048 + kk] = h;
        Wtl[(size_t)(nw + ty + 8 * i) * 2048 + kk] = l;
    }
}

// ---------------------------------------------------------------------------
// bf16 3-split GEMM, CTA tile 128m x 256n, warp tile 64x64 (8 warps 2x4).
// K=2048 in 64 chunks of 32, cp.async double buffered.
// Per buffer (48KB): Ah @0 (8K), Al @8K, Bh @16K (16K), Bl @32K (16K).
// Smem rows of 64B, 16B-chunk swizzle c' = c ^ ((row>>1)&3).
// mode 0: f32 out; mode 1: split-bf16 out (Ch/Cl).
// ---------------------------------------------------------------------------
#define GBUF 49152
#define GEMM_SMEM (2 * GBUF)

__global__ __launch_bounds__(256) void bf16gemm(
    const u16* __restrict__ Ahg, const u16* __restrict__ Alg,
    const u16* __restrict__ Bhg, const u16* __restrict__ Blg,
    int Nout, int mode, float* __restrict__ Cf,
    u16* __restrict__ Ch, u16* __restrict__ Cl)
{
    extern __shared__ char sm[];
    const u32 sb = (u32)__cvta_generic_to_shared(sm);
    const int tid = threadIdx.x, lane = tid & 31, warp = tid >> 5;
    const int warp_m = warp >> 2;    // 0..1 -> 64 rows each
    const int warp_n = warp & 3;     // 0..3 -> 64 cols each
    const int m0 = blockIdx.y * 128;
    const int n0 = blockIdx.x * 256;
    const int lt = lane >> 3, l7 = lane & 7;

    float acc[4][8][4];
#pragma unroll
    for (int mt = 0; mt < 4; mt++)
#pragma unroll
        for (int n8 = 0; n8 < 8; n8++)
#pragma unroll
            for (int e = 0; e < 4; e++) acc[mt][n8][e] = 0.0f;

    auto stage = [&](int c, int p) {
        const int kc = c * 32;
        const u32 b = sb + (u32)p * GBUF;
        // A hi/lo: 128 rows x 64B
#pragma unroll
        for (int j = 0; j < 2; j++) {
            int e = j * 256 + tid;
            int r = e >> 2, cc = e & 3;
            u32 so = (u32)(r * 64 + ((cc ^ ((r >> 1) & 3)) << 4));
            const size_t ga = (size_t)(m0 + r) * 2048 + kc + cc * 8;
            cpasync16(b + so,        Ahg + ga);
            cpasync16(b + 8192 + so, Alg + ga);
        }
        // B hi/lo: 256 rows x 64B
#pragma unroll
        for (int j = 0; j < 4; j++) {
            int e = j * 256 + tid;
            int r = e >> 2, cc = e & 3;
            u32 so = (u32)(r * 64 + ((cc ^ ((r >> 1) & 3)) << 4));
            const size_t gb = (size_t)(n0 + r) * 2048 + kc + cc * 8;
            cpasync16(b + 16384 + so, Bhg + gb);
            cpasync16(b + 32768 + so, Blg + gb);
        }
        CP_COMMIT();
    };

    stage(0, 0);

    for (int c = 0; c < 64; c++) {
        const int p = c & 1;
        if (c + 1 < 64) { stage(c + 1, p ^ 1); CP_WAIT1(); }
        else            { CP_WAIT0(); }
        __syncthreads();

        const u32 base = sb + (u32)p * GBUF;
#pragma unroll
        for (int kk = 0; kk < 2; kk++) {
            // A fragments (m16k16): rows m0-7/k0-7, m8-15/k0-7, m0-7/k8-15, m8-15/k8-15
            unsigned ah[4][4], al[4][4];
#pragma unroll
            for (int mt = 0; mt < 4; mt++) {
                int row = warp_m * 64 + mt * 16 + ((lt & 1) << 3) + l7;
                int cc = kk * 2 + (lt >> 1);
                u32 a = base + (u32)(row * 64 + ((cc ^ ((row >> 1) & 3)) << 4));
                ldsm4(ah[mt], a);
                ldsm4(al[mt], a + 8192);
            }
#pragma unroll
            for (int nt = 0; nt < 4; nt++) {
                // B fragments (n16k16): n0-7/k0-7, n0-7/k8-15, n8-15/k0-7, n8-15/k8-15
                unsigned bh[4], bl[4];
                int row = warp_n * 64 + nt * 16 + (((lt >> 1) & 1) << 3) + l7;
                int cc = kk * 2 + (lt & 1);
                u32 ba = base + 16384 + (u32)(row * 64 + ((cc ^ ((row >> 1) & 3)) << 4));
                ldsm4(bh, ba);
                ldsm4(bl, ba + 16384);
#pragma unroll
                for (int mt = 0; mt < 4; mt++) {
                    mma_bf16(acc[mt][2 * nt],     ah[mt], bh[0], bh[1]);
                    mma_bf16(acc[mt][2 * nt],     ah[mt], bl[0], bl[1]);
                    mma_bf16(acc[mt][2 * nt],     al[mt], bh[0], bh[1]);
                    mma_bf16(acc[mt][2 * nt + 1], ah[mt], bh[2], bh[3]);
                    mma_bf16(acc[mt][2 * nt + 1], ah[mt], bl[2], bl[3]);
                    mma_bf16(acc[mt][2 * nt + 1], al[mt], bh[2], bh[3]);
                }
            }
        }
        __syncthreads();
    }

    // epilogue
    const int lq = lane >> 2, lr = lane & 3;
#pragma unroll
    for (int mt = 0; mt < 4; mt++) {
        const int r0 = m0 + warp_m * 64 + mt * 16 + lq;
#pragma unroll
        for (int n8 = 0; n8 < 8; n8++) {
            const int col = n0 + warp_n * 64 + n8 * 8 + 2 * lr;
            if (mode == 0) {
                *(float2*)&Cf[(size_t)r0 * Nout + col] =
                    make_float2(acc[mt][n8][0], acc[mt][n8][1]);
                *(float2*)&Cf[(size_t)(r0 + 8) * Nout + col] =
                    make_float2(acc[mt][n8][2], acc[mt][n8][3]);
            } else {
                u16 h0, l0, h1, l1;
                bsplit(acc[mt][n8][0], h0, l0);
                bsplit(acc[mt][n8][1], h1, l1);
                *(u32*)&Ch[(size_t)r0 * Nout + col] = (u32)h0 | ((u32)h1 << 16);
                *(u32*)&Cl[(size_t)r0 * Nout + col] = (u32)l0 | ((u32)l1 << 16);
                bsplit(acc[mt][n8][2], h0, l0);
                bsplit(acc[mt][n8][3], h1, l1);
                *(u32*)&Ch[(size_t)(r0 + 8) * Nout + col] = (u32)h0 | ((u32)h1 << 16);
                *(u32*)&Cl[(size_t)(r0 + 8) * Nout + col] = (u32)l0 | ((u32)l1 << 16);
            }
        }
    }
}

// ---------------------------------------------------------------------------
// Tensor-core flash attention (R3-proven math; bf16 hi/lo I/O) — unchanged.
// ---------------------------------------------------------------------------
#define SOFTMAX_SCALE 0.08838834764831845f
#define NEG_BIG (-3.0e38f)
#define TS 136

#define QH_B 0
#define QL_B 34816
#define KH_B 69632
#define KL_B 87040
#define VH_B 104448
#define VL_B 121856
#define ATTN_SMEM_BYTES 139264

__device__ __forceinline__ void split2(float a, float b, unsigned& hi, unsigned& lo) {
    __nv_bfloat16 ah = __float2bfloat16_rn(a);
    __nv_bfloat16 bh = __float2bfloat16_rn(b);
    float af = __bfloat162float(ah), bf = __bfloat162float(bh);
    __nv_bfloat16 al = __float2bfloat16_rn(a - af);
    __nv_bfloat16 bl = __float2bfloat16_rn(b - bf);
    hi = (unsigned)__bfloat16_as_ushort(ah) | ((unsigned)__bfloat16_as_ushort(bh) << 16);
    lo = (unsigned)__bfloat16_as_ushort(al) | ((unsigned)__bfloat16_as_ushort(bl) << 16);
}

__global__ __launch_bounds__(256) void attn_mma()
{
    extern __shared__ unsigned short smb[];
    unsigned short* Qh = smb;
    unsigned short* Ql = smb + 17408;
    unsigned short* Kh = smb + 34816;
    unsigned short* Kl = smb + 43520;
    unsigned short* Vh = smb + 52224;
    unsigned short* Vl = smb + 60928;

    const int tid  = threadIdx.x;
    const int lane = tid & 31;
    const int w    = tid >> 5;

    const int b  = blockIdx.z;
    const int h  = blockIdx.y;
    const int m0 = gridDim.x - 1 - blockIdx.x;
    const int t0 = m0 * 128;
    const int kv = h >> 2;

    const unsigned sbase = (unsigned)__cvta_generic_to_shared(smb);

    const u16* Qhg = g_Qh + (size_t)(b * Tt + t0) * Cc + h * HD;
    const u16* Qlg = g_Ql + (size_t)(b * Tt + t0) * Cc + h * HD;
#pragma unroll
    for (int p = 0; p < 16; p++) {
        int idx = tid + p * 256;
        int r = idx >> 5;
        int c4 = (idx & 31) << 2;
        *(uint2*)&Qh[r * TS + c4] = *(const uint2*)&Qhg[(size_t)r * Cc + c4];
        *(uint2*)&Ql[r * TS + c4] = *(const uint2*)&Qlg[(size_t)r * Cc + c4];
    }

    float oacc[16][4];
#pragma unroll
    for (int i = 0; i < 16; i++)
#pragma unroll
        for (int e = 0; e < 4; e++) oacc[i][e] = 0.0f;
    float mrun0 = NEG_BIG, mrun1 = NEG_BIG, lrun0 = 0.0f, lrun1 = 0.0f;

    const int nkt = 2 * m0 + 2;
    const u16* Khg = g_Kh + (size_t)(b * Tt) * 512 + kv * HD;
    const u16* Klg = g_Kl + (size_t)(b * Tt) * 512 + kv * HD;
    const u16* Vhg = g_Vh + (size_t)(b * Tt) * 512 + kv * HD;
    const u16* Vlg = g_Vl + (size_t)(b * Tt) * 512 + kv * HD;

    const int lt = lane >> 3;
    const int l7 = lane & 7;

    for (int kt = 0; kt < nkt; kt++) {
        const int j0 = kt * 64;
        __syncthreads();

#pragma unroll
        for (int p = 0; p < 8; p++) {
            int idx = tid + p * 256;
            int r = idx >> 5;
            int c4 = (idx & 31) << 2;
            const size_t gi = (size_t)(j0 + r) * 512 + c4;
            *(uint2*)&Kh[r * TS + c4] = *(const uint2*)&Khg[gi];
            *(uint2*)&Kl[r * TS + c4] = *(const uint2*)&Klg[gi];
            *(uint2*)&Vh[r * TS + c4] = *(const uint2*)&Vhg[gi];
            *(uint2*)&Vl[r * TS + c4] = *(const uint2*)&Vlg[gi];
        }
        __syncthreads();

        float sacc[8][4];
#pragma unroll
        for (int i = 0; i < 8; i++)
#pragma unroll
            for (int e = 0; e < 4; e++) sacc[i][e] = 0.0f;

#pragma unroll
        for (int kk = 0; kk < 8; kk++) {
            const int k0 = kk * 16;
            unsigned ah[4], al[4];
            {
                int row = w * 16 + ((lt & 1) << 3) + l7;
                int col = k0 + ((lt >> 1) << 3);
                unsigned addr = sbase + QH_B + (unsigned)(row * TS + col) * 2;
                ldsm4(ah, addr);
                ldsm4(al, addr + (QL_B - QH_B));
            }
#pragma unroll
            for (int g = 0; g < 4; g++) {
                unsigned bh[4], bl[4];
                int row = g * 16 + (((lt >> 1) & 1) << 3) + l7;
                int col = k0 + ((lt & 1) << 3);
                unsigned addr = sbase + KH_B + (unsigned)(row * TS + col) * 2;
                ldsm4(bh, addr);
                ldsm4(bl, addr + (KL_B - KH_B));
                mma_bf16(sacc[2 * g],     ah, bh[0], bh[1]);
                mma_bf16(sacc[2 * g],     ah, bl[0], bl[1]);
                mma_bf16(sacc[2 * g],     al, bh[0], bh[1]);
                mma_bf16(sacc[2 * g + 1], ah, bh[2], bh[3]);
                mma_bf16(sacc[2 * g + 1], ah, bl[2], bl[3]);
                mma_bf16(sacc[2 * g + 1], al, bh[2], bh[3]);
            }
        }

        const bool diag = (kt >= nkt - 2);
        float mx0 = NEG_BIG, mx1 = NEG_BIG;
        const int rbase = t0 + w * 16 + (lane >> 2);
        const int cbase = j0 + 2 * (lane & 3);
#pragma unroll
        for (int nt = 0; nt < 8; nt++) {
#pragma unroll
            for (int e = 0; e < 4; e++) {
                float s = sacc[nt][e] * SOFTMAX_SCALE;
                if (diag) {
                    int col = cbase + nt * 8 + (e & 1);
                    int row = rbase + ((e & 2) << 2);
                    if (col > row) s = NEG_BIG;
                }
                sacc[nt][e] = s;
                if (e < 2) mx0 = fmaxf(mx0, s);
                else       mx1 = fmaxf(mx1, s);
            }
        }
        mx0 = fmaxf(mx0, __shfl_xor_sync(0xffffffffu, mx0, 1));
        mx0 = fmaxf(mx0, __shfl_xor_sync(0xffffffffu, mx0, 2));
        mx1 = fmaxf(mx1, __shfl_xor_sync(0xffffffffu, mx1, 1));
        mx1 = fmaxf(mx1, __shfl_xor_sync(0xffffffffu, mx1, 2));

        const float mn0 = fmaxf(mrun0, mx0);
        const float mn1 = fmaxf(mrun1, mx1);
        const float al0 = __expf(mrun0 - mn0);
        const float al1 = __expf(mrun1 - mn1);
        float rs0 = 0.0f, rs1 = 0.0f;
#pragma unroll
        for (int nt = 0; nt < 8; nt++) {
#pragma unroll
            for (int e = 0; e < 4; e++) {
                float p = __expf(sacc[nt][e] - (e < 2 ? mn0 : mn1));
                sacc[nt][e] = p;
                if (e < 2) rs0 += p;
                else       rs1 += p;
            }
        }
        rs0 += __shfl_xor_sync(0xffffffffu, rs0, 1);
        rs0 += __shfl_xor_sync(0xffffffffu, rs0, 2);
        rs1 += __shfl_xor_sync(0xffffffffu, rs1, 1);
        rs1 += __shfl_xor_sync(0xffffffffu, rs1, 2);
        lrun0 = lrun0 * al0 + rs0;
        lrun1 = lrun1 * al1 + rs1;
        mrun0 = mn0;
        mrun1 = mn1;
#pragma unroll
        for (int i = 0; i < 16; i++) {
            oacc[i][0] *= al0;
            oacc[i][1] *= al0;
            oacc[i][2] *= al1;
            oacc[i][3] *= al1;
        }

#pragma unroll
        for (int kk = 0; kk < 4; kk++) {
            unsigned aph[4], apl[4];
            split2(sacc[2 * kk][0],     sacc[2 * kk][1],     aph[0], apl[0]);
            split2(sacc[2 * kk][2],     sacc[2 * kk][3],     aph[1], apl[1]);
            split2(sacc[2 * kk + 1][0], sacc[2 * kk + 1][1], aph[2], apl[2]);
            split2(sacc[2 * kk + 1][2], sacc[2 * kk + 1][3], aph[3], apl[3]);
#pragma unroll
            for (int g = 0; g < 8; g++) {
                unsigned bh[4], bl[4];
                int row = kk * 16 + ((lt & 1) << 3) + l7;
                int col = g * 16 + (((lt >> 1) & 1) << 3);
                unsigned addr = sbase + VH_B + (unsigned)(row * TS + col) * 2;
                ldsm4t(bh, addr);
                ldsm4t(bl, addr + (VL_B - VH_B));
                mma_bf16(oacc[2 * g],     aph, bh[0], bh[1]);
                mma_bf16(oacc[2 * g],     aph, bl[0], bl[1]);
                mma_bf16(oacc[2 * g],     apl, bh[0], bh[1]);
                mma_bf16(oacc[2 * g + 1], aph, bh[2], bh[3]);
                mma_bf16(oacc[2 * g + 1], aph, bl[2], bl[3]);
                mma_bf16(oacc[2 * g + 1], apl, bh[2], bh[3]);
            }
        }
    }

    // normalize + write Y as split bf16
    const float i0 = 1.0f / lrun0;
    const float i1 = 1.0f / lrun1;
    const size_t rowg = (size_t)(b * Tt + t0 + w * 16 + (lane >> 2));
#pragma unroll
    for (int nt = 0; nt < 16; nt++) {
        int col = h * HD + nt * 8 + 2 * (lane & 3);
        u16 h0, l0, h1, l1;
        bsplit(oacc[nt][0] * i0, h0, l0);
        bsplit(oacc[nt][1] * i0, h1, l1);
        *(u32*)&g_Yh[rowg * Cc + col] = (u32)h0 | ((u32)h1 << 16);
        *(u32*)&g_Yl[rowg * Cc + col] = (u32)l0 | ((u32)l1 << 16);
        bsplit(oacc[nt][2] * i1, h0, l0);
        bsplit(oacc[nt][3] * i1, h1, l1);
        *(u32*)&g_Yh[(rowg + 8) * Cc + col] = (u32)h0 | ((u32)h1 << 16);
        *(u32*)&g_Yl[(rowg + 8) * Cc + col] = (u32)l0 | ((u32)l1 << 16);
    }
}

// ---------------------------------------------------------------------------
// Launch
// ---------------------------------------------------------------------------
extern "C" void kernel_launch(void* const* d_in, const int* in_sizes, int n_in,
                              void* d_out, int out_size)
{
    const float* x  = (const float*)d_in[0];
    const float* Wq = (const float*)d_in[1];
    const float* Wk = (const float*)d_in[2];
    const float* Wv = (const float*)d_in[3];
    const float* Wo = (const float*)d_in[4];
    float* out = (float*)d_out;

    void *pxh, *pxl, *pWqh, *pWql, *pWkh, *pWkl, *pWvh, *pWvl, *pWoh, *pWol;
    void *pQh, *pQl, *pKh, *pKl, *pVh, *pVl, *pYh, *pYl;
    cudaGetSymbolAddress(&pxh, g_xh);   cudaGetSymbolAddress(&pxl, g_xl);
    cudaGetSymbolAddress(&pWqh, g_WqTh); cudaGetSymbolAddress(&pWql, g_WqTl);
    cudaGetSymbolAddress(&pWkh, g_WkTh); cudaGetSymbolAddress(&pWkl, g_WkTl);
    cudaGetSymbolAddress(&pWvh, g_WvTh); cudaGetSymbolAddress(&pWvl, g_WvTl);
    cudaGetSymbolAddress(&pWoh, g_WoTh); cudaGetSymbolAddress(&pWol, g_WoTl);
    cudaGetSymbolAddress(&pQh, g_Qh);   cudaGetSymbolAddress(&pQl, g_Ql);
    cudaGetSymbolAddress(&pKh, g_Kh);   cudaGetSymbolAddress(&pKl, g_Kl);
    cudaGetSymbolAddress(&pVh, g_Vh);   cudaGetSymbolAddress(&pVl, g_Vl);
    cudaGetSymbolAddress(&pYh, g_Yh);   cudaGetSymbolAddress(&pYl, g_Yl);

    // prep: split x, transpose+split weights
    split_x_k<<<(Mrows * Cc) / 8 / 256, 256>>>(x, (u16*)pxh, (u16*)pxl);
    tsplit_k<<<dim3(2048 / 32, 2048 / 32), dim3(32, 8)>>>(Wq, (u16*)pWqh, (u16*)pWql, 2048);
    tsplit_k<<<dim3(512 / 32, 2048 / 32), dim3(32, 8)>>>(Wk, (u16*)pWkh, (u16*)pWkl, 512);
    tsplit_k<<<dim3(512 / 32, 2048 / 32), dim3(32, 8)>>>(Wv, (u16*)pWvh, (u16*)pWvl, 512);
    tsplit_k<<<dim3(2048 / 32, 2048 / 32), dim3(32, 8)>>>(Wo, (u16*)pWoh, (u16*)pWol, 2048);

    cudaFuncSetAttribute(bf16gemm, cudaFuncAttributeMaxDynamicSharedMemorySize, GEMM_SMEM);

    // projections (split-bf16 out for attention)
    bf16gemm<<<dim3(2048 / 256, Mrows / 128), 256, GEMM_SMEM>>>(
        (const u16*)pxh, (const u16*)pxl, (const u16*)pWqh, (const u16*)pWql,
        2048, 1, nullptr, (u16*)pQh, (u16*)pQl);
    bf16gemm<<<dim3(512 / 256, Mrows / 128), 256, GEMM_SMEM>>>(
        (const u16*)pxh, (const u16*)pxl, (const u16*)pWkh, (const u16*)pWkl,
        512, 1, nullptr, (u16*)pKh, (u16*)pKl);
    bf16gemm<<<dim3(512 / 256, Mrows / 128), 256, GEMM_SMEM>>>(
        (const u16*)pxh, (const u16*)pxl, (const u16*)pWvh, (const u16*)pWvl,
        512, 1, nullptr, (u16*)pVh, (u16*)pVl);

    // attention
    cudaFuncSetAttribute(attn_mma, cudaFuncAttributeMaxDynamicSharedMemorySize,
                         ATTN_SMEM_BYTES);
    attn_mma<<<dim3(Tt / 128, NH, Bb), 256, ATTN_SMEM_BYTES>>>();

    // output projection (f32 out)
    bf16gemm<<<dim3(2048 / 256, Mrows / 128), 256, GEMM_SMEM>>>(
        (const u16*)pYh, (const u16*)pYl, (const u16*)pWoh, (const u16*)pWol,
        2048, 0, out, nullptr, nullptr);
}

// round 8
// speedup vs baseline: 1.8534x; 1.8534x over previous
#include <cuda_runtime.h>
#include <cuda_bf16.h>
#include <cuda_fp16.h>
#include <math.h>

// Problem constants
#define Bb   2
#define Tt   2048
#define Cc   2048
#define NH   16
#define NKV  4
#define HD   128
#define Mrows (Bb * Tt)        // 4096

typedef unsigned short u16;
typedef unsigned int   u32;

// ---------------------------------------------------------------------------
// Scratch (device globals; allocation-free)
// ---------------------------------------------------------------------------
__device__ u16 g_xf[(size_t)Mrows * Cc];                 // x, fp16
__device__ u16 g_WqTf[(size_t)Cc * Cc];                  // W^T, fp16
__device__ u16 g_WkTf[(size_t)512 * Cc];
__device__ u16 g_WvTf[(size_t)512 * Cc];
__device__ u16 g_WoTf[(size_t)Cc * Cc];
__device__ u16 g_Qh[(size_t)Mrows * Cc],  g_Ql[(size_t)Mrows * Cc];   // split bf16
__device__ u16 g_Kh[(size_t)Mrows * 512], g_Kl[(size_t)Mrows * 512];
__device__ u16 g_Vh[(size_t)Mrows * 512], g_Vl[(size_t)Mrows * 512];
__device__ u16 g_Yf[(size_t)Mrows * Cc];                 // attention out, fp16

// ---------------------------------------------------------------------------
// Helpers
// ---------------------------------------------------------------------------
__device__ __forceinline__ void bsplit(float f, u16& h, u16& l) {
    __nv_bfloat16 bh = __float2bfloat16_rn(f);
    float fh = __bfloat162float(bh);
    __nv_bfloat16 bl = __float2bfloat16_rn(f - fh);
    h = __bfloat16_as_ushort(bh);
    l = __bfloat16_as_ushort(bl);
}
__device__ __forceinline__ u16 f2h(float f) {
    return __half_as_ushort(__float2half_rn(f));
}

__device__ __forceinline__ void ldsm4(unsigned* r, unsigned addr) {
    asm volatile("ldmatrix.sync.aligned.m8n8.x4.shared.b16 {%0,%1,%2,%3}, [%4];\n"
                 : "=r"(r[0]), "=r"(r[1]), "=r"(r[2]), "=r"(r[3]) : "r"(addr));
}
__device__ __forceinline__ void ldsm4t(unsigned* r, unsigned addr) {
    asm volatile("ldmatrix.sync.aligned.m8n8.x4.trans.shared.b16 {%0,%1,%2,%3}, [%4];\n"
                 : "=r"(r[0]), "=r"(r[1]), "=r"(r[2]), "=r"(r[3]) : "r"(addr));
}
__device__ __forceinline__ void mma_bf16(float* c, const unsigned* a,
                                         unsigned b0, unsigned b1) {
    asm volatile(
        "mma.sync.aligned.m16n8k16.row.col.f32.bf16.bf16.f32 "
        "{%0,%1,%2,%3}, {%4,%5,%6,%7}, {%8,%9}, {%0,%1,%2,%3};\n"
        : "+f"(c[0]), "+f"(c[1]), "+f"(c[2]), "+f"(c[3])
        : "r"(a[0]), "r"(a[1]), "r"(a[2]), "r"(a[3]), "r"(b0), "r"(b1));
}
__device__ __forceinline__ void mma_f16(float* c, const unsigned* a,
                                        unsigned b0, unsigned b1) {
    asm volatile(
        "mma.sync.aligned.m16n8k16.row.col.f32.f16.f16.f32 "
        "{%0,%1,%2,%3}, {%4,%5,%6,%7}, {%8,%9}, {%0,%1,%2,%3};\n"
        : "+f"(c[0]), "+f"(c[1]), "+f"(c[2]), "+f"(c[3])
        : "r"(a[0]), "r"(a[1]), "r"(a[2]), "r"(a[3]), "r"(b0), "r"(b1));
}

__device__ __forceinline__ void cpasync16(u32 dst, const void* src) {
    asm volatile("cp.async.cg.shared.global [%0], [%1], 16;"
                 :: "r"(dst), "l"(src) : "memory");
}
#define CP_COMMIT() asm volatile("cp.async.commit_group;" ::: "memory")
#define CP_WAIT1()  asm volatile("cp.async.wait_group 1;" ::: "memory")
#define CP_WAIT0()  asm volatile("cp.async.wait_group 0;" ::: "memory")

// ---------------------------------------------------------------------------
// Prep kernels
// ---------------------------------------------------------------------------
__global__ __launch_bounds__(256) void conv_x(const float* __restrict__ x,
                                              u16* __restrict__ xf)
{
    size_t i = ((size_t)blockIdx.x * 256 + threadIdx.x) * 8;
    float4 a = *(const float4*)(x + i);
    float4 b = *(const float4*)(x + i + 4);
    float f[8] = {a.x, a.y, a.z, a.w, b.x, b.y, b.z, b.w};
    uint4 H;
    H.x = (u32)f2h(f[0]) | ((u32)f2h(f[1]) << 16);
    H.y = (u32)f2h(f[2]) | ((u32)f2h(f[3]) << 16);
    H.z = (u32)f2h(f[4]) | ((u32)f2h(f[5]) << 16);
    H.w = (u32)f2h(f[6]) | ((u32)f2h(f[7]) << 16);
    *(uint4*)(xf + i) = H;
}

// W [K=2048, N] f32 -> WT [N, 2048] fp16
__global__ __launch_bounds__(256) void tsplit_f(const float* __restrict__ W,
                                                u16* __restrict__ Wtf, int N)
{
    __shared__ float t[32][33];
    const int tx = threadIdx.x, ty = threadIdx.y;
    const int n = blockIdx.x * 32 + tx;
    const int k0 = blockIdx.y * 32;
#pragma unroll
    for (int i = 0; i < 4; i++)
        t[ty + 8 * i][tx] = W[(size_t)(k0 + ty + 8 * i) * N + n];
    __syncthreads();
    const int nw = blockIdx.x * 32;
    const int kk = k0 + tx;
#pragma unroll
    for (int i = 0; i < 4; i++)
        Wtf[(size_t)(nw + ty + 8 * i) * 2048 + kk] = f2h(t[tx][ty + 8 * i]);
}

// ---------------------------------------------------------------------------
// fp16 GEMM via mma.sync + ldmatrix + cp.async double buffering.
// C[128m x 128n] per CTA, warp tile 64x32 (8 warps 2x4), K=2048 in 64 chunks.
// Per buffer (16KB): A @0 (8K), B @8K (8K). Two buffers = 32KB.
// Smem rows of 64B (32 fp16), 16B chunk swizzle c' = c ^ ((row>>1)&3).
// mode 0: f32 out; mode 1: split-bf16 out (Ch/Cl) for attention input.
// ---------------------------------------------------------------------------
#define GBUF 16384
#define GEMM_SMEM (2 * GBUF)

__global__ __launch_bounds__(256, 2) void f16gemm(
    const u16* __restrict__ Ag, const u16* __restrict__ Bg,
    int Nout, int mode, float* __restrict__ Cf,
    u16* __restrict__ Ch, u16* __restrict__ Cl)
{
    extern __shared__ char sm[];
    const u32 sb = (u32)__cvta_generic_to_shared(sm);
    const int tid = threadIdx.x, lane = tid & 31, warp = tid >> 5;
    const int warp_m = warp >> 2;    // 0..1 -> 64 rows each
    const int warp_n = warp & 3;     // 0..3 -> 32 cols each
    const int m0 = blockIdx.y * 128;
    const int n0 = blockIdx.x * 128;
    const int lt = lane >> 3, l7 = lane & 7;

    float acc[4][4][4];
#pragma unroll
    for (int mt = 0; mt < 4; mt++)
#pragma unroll
        for (int n8 = 0; n8 < 4; n8++)
#pragma unroll
            for (int e = 0; e < 4; e++) acc[mt][n8][e] = 0.0f;

    auto stage = [&](int c, int p) {
        const int kc = c * 32;
        const u32 b = sb + (u32)p * GBUF;
#pragma unroll
        for (int j = 0; j < 2; j++) {
            int e = j * 256 + tid;
            int r = e >> 2, cc = e & 3;
            u32 so = (u32)(r * 64 + ((cc ^ ((r >> 1) & 3)) << 4));
            cpasync16(b + so,        Ag + (size_t)(m0 + r) * 2048 + kc + cc * 8);
            cpasync16(b + 8192 + so, Bg + (size_t)(n0 + r) * 2048 + kc + cc * 8);
        }
        CP_COMMIT();
    };

    stage(0, 0);

    for (int c = 0; c < 64; c++) {
        const int p = c & 1;
        if (c + 1 < 64) { stage(c + 1, p ^ 1); CP_WAIT1(); }
        else            { CP_WAIT0(); }
        __syncthreads();

        const u32 base = sb + (u32)p * GBUF;
#pragma unroll
        for (int kk = 0; kk < 2; kk++) {
            // A fragments (m16k16)
            unsigned af[4][4];
#pragma unroll
            for (int mt = 0; mt < 4; mt++) {
                int row = warp_m * 64 + mt * 16 + ((lt & 1) << 3) + l7;
                int cc = kk * 2 + (lt >> 1);
                ldsm4(af[mt], base + (u32)(row * 64 + ((cc ^ ((row >> 1) & 3)) << 4)));
            }
#pragma unroll
            for (int nt = 0; nt < 2; nt++) {
                // B fragments (n16k16)
                unsigned bf[4];
                int row = warp_n * 32 + nt * 16 + (((lt >> 1) & 1) << 3) + l7;
                int cc = kk * 2 + (lt & 1);
                ldsm4(bf, base + 8192 + (u32)(row * 64 + ((cc ^ ((row >> 1) & 3)) << 4)));
#pragma unroll
                for (int mt = 0; mt < 4; mt++) {
                    mma_f16(acc[mt][2 * nt],     af[mt], bf[0], bf[1]);
                    mma_f16(acc[mt][2 * nt + 1], af[mt], bf[2], bf[3]);
                }
            }
        }
        __syncthreads();
    }

    // epilogue
    const int lq = lane >> 2, lr = lane & 3;
#pragma unroll
    for (int mt = 0; mt < 4; mt++) {
        const int r0 = m0 + warp_m * 64 + mt * 16 + lq;
#pragma unroll
        for (int n8 = 0; n8 < 4; n8++) {
            const int col = n0 + warp_n * 32 + n8 * 8 + 2 * lr;
            if (mode == 0) {
                *(float2*)&Cf[(size_t)r0 * Nout + col] =
                    make_float2(acc[mt][n8][0], acc[mt][n8][1]);
                *(float2*)&Cf[(size_t)(r0 + 8) * Nout + col] =
                    make_float2(acc[mt][n8][2], acc[mt][n8][3]);
            } else {
                u16 h0, l0, h1, l1;
                bsplit(acc[mt][n8][0], h0, l0);
                bsplit(acc[mt][n8][1], h1, l1);
                *(u32*)&Ch[(size_t)r0 * Nout + col] = (u32)h0 | ((u32)h1 << 16);
                *(u32*)&Cl[(size_t)r0 * Nout + col] = (u32)l0 | ((u32)l1 << 16);
                bsplit(acc[mt][n8][2], h0, l0);
                bsplit(acc[mt][n8][3], h1, l1);
                *(u32*)&Ch[(size_t)(r0 + 8) * Nout + col] = (u32)h0 | ((u32)h1 << 16);
                *(u32*)&Cl[(size_t)(r0 + 8) * Nout + col] = (u32)l0 | ((u32)l1 << 16);
            }
        }
    }
}

// ---------------------------------------------------------------------------
// Tensor-core flash attention (R3-proven math; split-bf16 in, fp16 out)
// ---------------------------------------------------------------------------
#define SOFTMAX_SCALE 0.08838834764831845f
#define NEG_BIG (-3.0e38f)
#define TS 136

#define QH_B 0
#define QL_B 34816
#define KH_B 69632
#define KL_B 87040
#define VH_B 104448
#define VL_B 121856
#define ATTN_SMEM_BYTES 139264

__device__ __forceinline__ void split2(float a, float b, unsigned& hi, unsigned& lo) {
    __nv_bfloat16 ah = __float2bfloat16_rn(a);
    __nv_bfloat16 bh = __float2bfloat16_rn(b);
    float af = __bfloat162float(ah), bf = __bfloat162float(bh);
    __nv_bfloat16 al = __float2bfloat16_rn(a - af);
    __nv_bfloat16 bl = __float2bfloat16_rn(b - bf);
    hi = (unsigned)__bfloat16_as_ushort(ah) | ((unsigned)__bfloat16_as_ushort(bh) << 16);
    lo = (unsigned)__bfloat16_as_ushort(al) | ((unsigned)__bfloat16_as_ushort(bl) << 16);
}

__global__ __launch_bounds__(256) void attn_mma()
{
    extern __shared__ unsigned short smb[];
    unsigned short* Qh = smb;
    unsigned short* Ql = smb + 17408;
    unsigned short* Kh = smb + 34816;
    unsigned short* Kl = smb + 43520;
    unsigned short* Vh = smb + 52224;
    unsigned short* Vl = smb + 60928;

    const int tid  = threadIdx.x;
    const int lane = tid & 31;
    const int w    = tid >> 5;

    const int b  = blockIdx.z;
    const int h  = blockIdx.y;
    const int m0 = gridDim.x - 1 - blockIdx.x;
    const int t0 = m0 * 128;
    const int kv = h >> 2;

    const unsigned sbase = (unsigned)__cvta_generic_to_shared(smb);

    const u16* Qhg = g_Qh + (size_t)(b * Tt + t0) * Cc + h * HD;
    const u16* Qlg = g_Ql + (size_t)(b * Tt + t0) * Cc + h * HD;
#pragma unroll
    for (int p = 0; p < 16; p++) {
        int idx = tid + p * 256;
        int r = idx >> 5;
        int c4 = (idx & 31) << 2;
        *(uint2*)&Qh[r * TS + c4] = *(const uint2*)&Qhg[(size_t)r * Cc + c4];
        *(uint2*)&Ql[r * TS + c4] = *(const uint2*)&Qlg[(size_t)r * Cc + c4];
    }

    float oacc[16][4];
#pragma unroll
    for (int i = 0; i < 16; i++)
#pragma unroll
        for (int e = 0; e < 4; e++) oacc[i][e] = 0.0f;
    float mrun0 = NEG_BIG, mrun1 = NEG_BIG, lrun0 = 0.0f, lrun1 = 0.0f;

    const int nkt = 2 * m0 + 2;
    const u16* Khg = g_Kh + (size_t)(b * Tt) * 512 + kv * HD;
    const u16* Klg = g_Kl + (size_t)(b * Tt) * 512 + kv * HD;
    const u16* Vhg = g_Vh + (size_t)(b * Tt) * 512 + kv * HD;
    const u16* Vlg = g_Vl + (size_t)(b * Tt) * 512 + kv * HD;

    const int lt = lane >> 3;
    const int l7 = lane & 7;

    for (int kt = 0; kt < nkt; kt++) {
        const int j0 = kt * 64;
        __syncthreads();

#pragma unroll
        for (int p = 0; p < 8; p++) {
            int idx = tid + p * 256;
            int r = idx >> 5;
            int c4 = (idx & 31) << 2;
            const size_t gi = (size_t)(j0 + r) * 512 + c4;
            *(uint2*)&Kh[r * TS + c4] = *(const uint2*)&Khg[gi];
            *(uint2*)&Kl[r * TS + c4] = *(const uint2*)&Klg[gi];
            *(uint2*)&Vh[r * TS + c4] = *(const uint2*)&Vhg[gi];
            *(uint2*)&Vl[r * TS + c4] = *(const uint2*)&Vlg[gi];
        }
        __syncthreads();

        float sacc[8][4];
#pragma unroll
        for (int i = 0; i < 8; i++)
#pragma unroll
            for (int e = 0; e < 4; e++) sacc[i][e] = 0.0f;

#pragma unroll
        for (int kk = 0; kk < 8; kk++) {
            const int k0 = kk * 16;
            unsigned ah[4], al[4];
            {
                int row = w * 16 + ((lt & 1) << 3) + l7;
                int col = k0 + ((lt >> 1) << 3);
                unsigned addr = sbase + QH_B + (unsigned)(row * TS + col) * 2;
                ldsm4(ah, addr);
                ldsm4(al, addr + (QL_B - QH_B));
            }
#pragma unroll
            for (int g = 0; g < 4; g++) {
                unsigned bh[4], bl[4];
                int row = g * 16 + (((lt >> 1) & 1) << 3) + l7;
                int col = k0 + ((lt & 1) << 3);
                unsigned addr = sbase + KH_B + (unsigned)(row * TS + col) * 2;
                ldsm4(bh, addr);
                ldsm4(bl, addr + (KL_B - KH_B));
                mma_bf16(sacc[2 * g],     ah, bh[0], bh[1]);
                mma_bf16(sacc[2 * g],     ah, bl[0], bl[1]);
                mma_bf16(sacc[2 * g],     al, bh[0], bh[1]);
                mma_bf16(sacc[2 * g + 1], ah, bh[2], bh[3]);
                mma_bf16(sacc[2 * g + 1], ah, bl[2], bl[3]);
                mma_bf16(sacc[2 * g + 1], al, bh[2], bh[3]);
            }
        }

        const bool diag = (kt >= nkt - 2);
        float mx0 = NEG_BIG, mx1 = NEG_BIG;
        const int rbase = t0 + w * 16 + (lane >> 2);
        const int cbase = j0 + 2 * (lane & 3);
#pragma unroll
        for (int nt = 0; nt < 8; nt++) {
#pragma unroll
            for (int e = 0; e < 4; e++) {
                float s = sacc[nt][e] * SOFTMAX_SCALE;
                if (diag) {
                    int col = cbase + nt * 8 + (e & 1);
                    int row = rbase + ((e & 2) << 2);
                    if (col > row) s = NEG_BIG;
                }
                sacc[nt][e] = s;
                if (e < 2) mx0 = fmaxf(mx0, s);
                else       mx1 = fmaxf(mx1, s);
            }
        }
        mx0 = fmaxf(mx0, __shfl_xor_sync(0xffffffffu, mx0, 1));
        mx0 = fmaxf(mx0, __shfl_xor_sync(0xffffffffu, mx0, 2));
        mx1 = fmaxf(mx1, __shfl_xor_sync(0xffffffffu, mx1, 1));
        mx1 = fmaxf(mx1, __shfl_xor_sync(0xffffffffu, mx1, 2));

        const float mn0 = fmaxf(mrun0, mx0);
        const float mn1 = fmaxf(mrun1, mx1);
        const float al0 = __expf(mrun0 - mn0);
        const float al1 = __expf(mrun1 - mn1);
        float rs0 = 0.0f, rs1 = 0.0f;
#pragma unroll
        for (int nt = 0; nt < 8; nt++) {
#pragma unroll
            for (int e = 0; e < 4; e++) {
                float p = __expf(sacc[nt][e] - (e < 2 ? mn0 : mn1));
                sacc[nt][e] = p;
                if (e < 2) rs0 += p;
                else       rs1 += p;
            }
        }
        rs0 += __shfl_xor_sync(0xffffffffu, rs0, 1);
        rs0 += __shfl_xor_sync(0xffffffffu, rs0, 2);
        rs1 += __shfl_xor_sync(0xffffffffu, rs1, 1);
        rs1 += __shfl_xor_sync(0xffffffffu, rs1, 2);
        lrun0 = lrun0 * al0 + rs0;
        lrun1 = lrun1 * al1 + rs1;
        mrun0 = mn0;
        mrun1 = mn1;
#pragma unroll
        for (int i = 0; i < 16; i++) {
            oacc[i][0] *= al0;
            oacc[i][1] *= al0;
            oacc[i][2] *= al1;
            oacc[i][3] *= al1;
        }

#pragma unroll
        for (int kk = 0; kk < 4; kk++) {
            unsigned aph[4], apl[4];
            split2(sacc[2 * kk][0],     sacc[2 * kk][1],     aph[0], apl[0]);
            split2(sacc[2 * kk][2],     sacc[2 * kk][3],     aph[1], apl[1]);
            split2(sacc[2 * kk + 1][0], sacc[2 * kk + 1][1], aph[2], apl[2]);
            split2(sacc[2 * kk + 1][2], sacc[2 * kk + 1][3], aph[3], apl[3]);
#pragma unroll
            for (int g = 0; g < 8; g++) {
                unsigned bh[4], bl[4];
                int row = kk * 16 + ((lt & 1) << 3) + l7;
                int col = g * 16 + (((lt >> 1) & 1) << 3);
                unsigned addr = sbase + VH_B + (unsigned)(row * TS + col) * 2;
                ldsm4t(bh, addr);
                ldsm4t(bl, addr + (VL_B - VH_B));
                mma_bf16(oacc[2 * g],     aph, bh[0], bh[1]);
                mma_bf16(oacc[2 * g],     aph, bl[0], bl[1]);
                mma_bf16(oacc[2 * g],     apl, bh[0], bh[1]);
                mma_bf16(oacc[2 * g + 1], aph, bh[2], bh[3]);
                mma_bf16(oacc[2 * g + 1], aph, bl[2], bl[3]);
                mma_bf16(oacc[2 * g + 1], apl, bh[2], bh[3]);
            }
        }
    }

    // normalize + write Y as fp16 (input to O-projection)
    const float i0 = 1.0f / lrun0;
    const float i1 = 1.0f / lrun1;
    const size_t rowg = (size_t)(b * Tt + t0 + w * 16 + (lane >> 2));
#pragma unroll
    for (int nt = 0; nt < 16; nt++) {
        int col = h * HD + nt * 8 + 2 * (lane & 3);
        *(u32*)&g_Yf[rowg * Cc + col] =
            (u32)f2h(oacc[nt][0] * i0) | ((u32)f2h(oacc[nt][1] * i0) << 16);
        *(u32*)&g_Yf[(rowg + 8) * Cc + col] =
            (u32)f2h(oacc[nt][2] * i1) | ((u32)f2h(oacc[nt][3] * i1) << 16);
    }
}

// ---------------------------------------------------------------------------
// Launch
// ---------------------------------------------------------------------------
extern "C" void kernel_launch(void* const* d_in, const int* in_sizes, int n_in,
                              void* d_out, int out_size)
{
    const float* x  = (const float*)d_in[0];
    const float* Wq = (const float*)d_in[1];
    const float* Wk = (const float*)d_in[2];
    const float* Wv = (const float*)d_in[3];
    const float* Wo = (const float*)d_in[4];
    float* out = (float*)d_out;

    void *pxf, *pWq, *pWk, *pWv, *pWo;
    void *pQh, *pQl, *pKh, *pKl, *pVh, *pVl, *pYf;
    cudaGetSymbolAddress(&pxf, g_xf);
    cudaGetSymbolAddress(&pWq, g_WqTf);
    cudaGetSymbolAddress(&pWk, g_WkTf);
    cudaGetSymbolAddress(&pWv, g_WvTf);
    cudaGetSymbolAddress(&pWo, g_WoTf);
    cudaGetSymbolAddress(&pQh, g_Qh);   cudaGetSymbolAddress(&pQl, g_Ql);
    cudaGetSymbolAddress(&pKh, g_Kh);   cudaGetSymbolAddress(&pKl, g_Kl);
    cudaGetSymbolAddress(&pVh, g_Vh);   cudaGetSymbolAddress(&pVl, g_Vl);
    cudaGetSymbolAddress(&pYf, g_Yf);

    // prep: fp16 x, transpose+fp16 weights
    conv_x<<<(Mrows * Cc) / 8 / 256, 256>>>(x, (u16*)pxf);
    tsplit_f<<<dim3(2048 / 32, 2048 / 32), dim3(32, 8)>>>(Wq, (u16*)pWq, 2048);
    tsplit_f<<<dim3(512 / 32, 2048 / 32), dim3(32, 8)>>>(Wk, (u16*)pWk, 512);
    tsplit_f<<<dim3(512 / 32, 2048 / 32), dim3(32, 8)>>>(Wv, (u16*)pWv, 512);
    tsplit_f<<<dim3(2048 / 32, 2048 / 32), dim3(32, 8)>>>(Wo, (u16*)pWo, 2048);

    cudaFuncSetAttribute(f16gemm, cudaFuncAttributeMaxDynamicSharedMemorySize, GEMM_SMEM);

    // projections (split-bf16 out for attention)
    f16gemm<<<dim3(2048 / 128, Mrows / 128), 256, GEMM_SMEM>>>(
        (const u16*)pxf, (const u16*)pWq, 2048, 1, nullptr, (u16*)pQh, (u16*)pQl);
    f16gemm<<<dim3(512 / 128, Mrows / 128), 256, GEMM_SMEM>>>(
        (const u16*)pxf, (const u16*)pWk, 512, 1, nullptr, (u16*)pKh, (u16*)pKl);
    f16gemm<<<dim3(512 / 128, Mrows / 128), 256, GEMM_SMEM>>>(
        (const u16*)pxf, (const u16*)pWv, 512, 1, nullptr, (u16*)pVh, (u16*)pVl);

    // attention
    cudaFuncSetAttribute(attn_mma, cudaFuncAttributeMaxDynamicSharedMemorySize,
                         ATTN_SMEM_BYTES);
    attn_mma<<<dim3(Tt / 128, NH, Bb), 256, ATTN_SMEM_BYTES>>>();

    // output projection (f32 out)
    f16gemm<<<dim3(2048 / 128, Mrows / 128), 256, GEMM_SMEM>>>(
        (const u16*)pYf, (const u16*)pWo, 2048, 0, out, nullptr, nullptr);
}